// round 3
// baseline (speedup 1.0000x reference)
#include <cuda_runtime.h>
#include <math.h>

#define BATCH   4
#define TLEN    512
#define EDIM    1024
#define VOCAB_N 32000
#define BEAM_N  64
#define RANK_N  32
#define MROWS   (BATCH * TLEN)   // 2048

// ---------------- scratch (static device globals; no runtime allocation) ----
__device__ int   g_beams[MROWS * BEAM_N];                       // 512 KB
__device__ float g_bemit[MROWS * BEAM_N];                       // 512 KB
__device__ float g_tm[BATCH * (TLEN - 1) * BEAM_N * BEAM_N];    // 33.5 MB

// ============================================================================
// 1) SGEMM: C[m,n] = sum_k A[m,k] * Bw[n,k] + bias[n]
//    A = modelout (2048 x 1024), Bw = W (32000 x 1024), both K-major (NT gemm)
//    128x128x16 tile, 256 threads, 8x8 register microtile.
// ============================================================================
__global__ void __launch_bounds__(256)
gemm_kernel(const float* __restrict__ A, const float* __restrict__ Bw,
            const float* __restrict__ bias, float* __restrict__ C)
{
    const int BM = 128, BN = 128, BK = 16;
    __shared__ float As[BK][BM];
    __shared__ float Bs[BK][BN];

    int tid  = threadIdx.x;
    int row0 = blockIdx.y * BM;
    int col0 = blockIdx.x * BN;
    int tx = tid & 15;        // 0..15 -> N microtiles
    int ty = tid >> 4;        // 0..15 -> M microtiles

    float acc[8][8];
#pragma unroll
    for (int i = 0; i < 8; i++)
#pragma unroll
        for (int j = 0; j < 8; j++) acc[i][j] = 0.f;

    for (int k0 = 0; k0 < EDIM; k0 += BK) {
        // load 128x16 of A and Bw, transposed into smem: 512 float4 each, 2/thread
#pragma unroll
        for (int i = 0; i < 2; i++) {
            int l  = tid + i * 256;
            int r  = l >> 2;     // row within tile (0..127)
            int c4 = l & 3;      // float4 within the 16-wide row
            float4 va = *(const float4*)(&A [(size_t)(row0 + r) * EDIM + k0 + c4 * 4]);
            As[c4 * 4 + 0][r] = va.x; As[c4 * 4 + 1][r] = va.y;
            As[c4 * 4 + 2][r] = va.z; As[c4 * 4 + 3][r] = va.w;
            float4 vb = *(const float4*)(&Bw[(size_t)(col0 + r) * EDIM + k0 + c4 * 4]);
            Bs[c4 * 4 + 0][r] = vb.x; Bs[c4 * 4 + 1][r] = vb.y;
            Bs[c4 * 4 + 2][r] = vb.z; Bs[c4 * 4 + 3][r] = vb.w;
        }
        __syncthreads();

#pragma unroll
        for (int k = 0; k < BK; k++) {
            float ra[8], rb[8];
            float4 a0 = *(const float4*)(&As[k][ty * 8]);
            float4 a1 = *(const float4*)(&As[k][ty * 8 + 4]);
            ra[0]=a0.x; ra[1]=a0.y; ra[2]=a0.z; ra[3]=a0.w;
            ra[4]=a1.x; ra[5]=a1.y; ra[6]=a1.z; ra[7]=a1.w;
            float4 b0 = *(const float4*)(&Bs[k][tx * 8]);
            float4 b1 = *(const float4*)(&Bs[k][tx * 8 + 4]);
            rb[0]=b0.x; rb[1]=b0.y; rb[2]=b0.z; rb[3]=b0.w;
            rb[4]=b1.x; rb[5]=b1.y; rb[6]=b1.z; rb[7]=b1.w;
#pragma unroll
            for (int i = 0; i < 8; i++)
#pragma unroll
                for (int j = 0; j < 8; j++)
                    acc[i][j] += ra[i] * rb[j];
        }
        __syncthreads();
    }

#pragma unroll
    for (int i = 0; i < 8; i++) {
        size_t rbase = (size_t)(row0 + ty * 8 + i) * VOCAB_N + col0 + tx * 8;
#pragma unroll
        for (int j = 0; j < 8; j++)
            C[rbase + j] = acc[i][j] + bias[col0 + tx * 8 + j];
    }
}

// ============================================================================
// 2) Exact top-64 per row via 4-pass radix select on order-preserving keys.
//    Target index forced to key=0xFFFFFFFF (matches "set to +inf" semantics).
//    Beam ORDER is irrelevant downstream (logsumexp is permutation-invariant).
// ============================================================================
__device__ __forceinline__ unsigned f2key(float x)
{
    unsigned u = __float_as_uint(x);
    return (u & 0x80000000u) ? ~u : (u | 0x80000000u);
}

__global__ void __launch_bounds__(256)
topk_kernel(const float* __restrict__ logits, const int* __restrict__ target)
{
    int row = blockIdx.x;
    const float* lrow = logits + (size_t)row * VOCAB_N;
    int tgt = target[row];
    int tid = threadIdx.x;

    __shared__ unsigned hist[256];
    __shared__ unsigned s_pref;
    __shared__ int s_want;
    __shared__ int cnt_gt, cnt_eq;

    if (tid == 0) { s_pref = 0u; s_want = BEAM_N; }
    __syncthreads();

    for (int pass = 0; pass < 4; pass++) {
        hist[tid] = 0;
        __syncthreads();
        unsigned pref = s_pref;
        int shift = 24 - pass * 8;
        for (int i = tid; i < VOCAB_N; i += 256) {
            unsigned key = (i == tgt) ? 0xFFFFFFFFu : f2key(lrow[i]);
            bool part = (pass == 0) || ((key >> (shift + 8)) == pref);
            if (part) atomicAdd(&hist[(key >> shift) & 0xFFu], 1u);
        }
        __syncthreads();
        if (tid == 0) {
            int want = s_want;
            unsigned cum = 0;
            for (int b = 255; b >= 0; b--) {
                unsigned c = hist[b];
                if (cum + c >= (unsigned)want) {
                    s_pref = (pref << 8) | (unsigned)b;
                    s_want = want - (int)cum;
                    break;
                }
                cum += c;
            }
        }
        __syncthreads();
    }

    unsigned thresh = s_pref;   // exact 64th-largest key
    int want = s_want;          // how many of the ==thresh keys to take
    int nGT  = BEAM_N - want;
    if (tid == 0) { cnt_gt = 0; cnt_eq = 0; }
    __syncthreads();

    for (int i = tid; i < VOCAB_N; i += 256) {
        unsigned key = (i == tgt) ? 0xFFFFFFFFu : f2key(lrow[i]);
        if (key > thresh) {
            int p = atomicAdd(&cnt_gt, 1);
            g_beams[row * BEAM_N + p] = i;
        } else if (key == thresh) {
            int p = atomicAdd(&cnt_eq, 1);
            if (p < want) g_beams[row * BEAM_N + nGT + p] = i;
        }
    }
    __syncthreads();

    if (tid < BEAM_N) {
        int idx = g_beams[row * BEAM_N + tid];
        g_bemit[row * BEAM_N + tid] = lrow[idx];  // original logit (not +inf)
    }
}

// ============================================================================
// 3) trans_mat[b,t,k,l] = dot(E1[beam[b,t,k]], E2[beam[b,t+1,l]])  (rank 32)
// ============================================================================
__global__ void __launch_bounds__(256)
transmat_kernel(const float* __restrict__ E1, const float* __restrict__ E2)
{
    int bt = blockIdx.x;           // 0 .. BATCH*(TLEN-1)-1
    int b  = bt / (TLEN - 1);
    int t  = bt % (TLEN - 1);
    int tid = threadIdx.x;

    __shared__ float s1[BEAM_N][RANK_N + 1];
    __shared__ float s2[BEAM_N][RANK_N + 1];

    const int* bm0 = g_beams + (size_t)(b * TLEN + t) * BEAM_N;
    const int* bm1 = bm0 + BEAM_N;

    for (int i = tid; i < BEAM_N * RANK_N; i += 256) {
        int k = i >> 5, r = i & 31;
        s1[k][r] = E1[(size_t)bm0[k] * RANK_N + r];
        s2[k][r] = E2[(size_t)bm1[k] * RANK_N + r];
    }
    __syncthreads();

    float* out = g_tm + (size_t)bt * (BEAM_N * BEAM_N);
    for (int o = tid; o < BEAM_N * BEAM_N; o += 256) {
        int kk = o >> 6, ll = o & 63;
        float acc = 0.f;
#pragma unroll
        for (int r = 0; r < RANK_N; r++) acc += s1[kk][r] * s2[ll][r];
        out[o] = acc;
    }
}

// ============================================================================
// 4) Forward recursion + numerator + final loss. One block per batch element.
// ============================================================================
__global__ void __launch_bounds__(64)
forward_kernel(const float* __restrict__ logits, const int* __restrict__ target,
               const float* __restrict__ E1, const float* __restrict__ E2,
               float* __restrict__ losses)
{
    int b = blockIdx.x;
    int l = threadIdx.x;
    __shared__ float sc[BEAM_N];
    __shared__ float red[BEAM_N];

    // ---- numerator: sum_t mask[t]*(emit[t] + (t>0 ? trans[t] : 0)) ----
    float np = 0.f;
    for (int t = l; t < TLEN; t += BEAM_N) {
        int tg = target[b * TLEN + t];
        if (tg != 0) {
            float e = logits[(size_t)(b * TLEN + t) * VOCAB_N + tg];
            float tr = 0.f;
            if (t > 0) {
                int tp = target[b * TLEN + t - 1];
#pragma unroll
                for (int r = 0; r < RANK_N; r++)
                    tr += E1[(size_t)tp * RANK_N + r] * E2[(size_t)tg * RANK_N + r];
            }
            np += e + tr;
        }
    }
    red[l] = np;
    sc[l]  = g_bemit[(size_t)(b * TLEN) * BEAM_N + l];   // score0 = beam_emit[:,0]
    __syncthreads();

    // ---- sequential scan over T ----
    for (int t = 1; t < TLEN; t++) {
        const float* tmrow = g_tm + (size_t)(b * (TLEN - 1) + t - 1) * (BEAM_N * BEAM_N);
        float v[BEAM_N];
        float mx = -3.4e38f;
#pragma unroll
        for (int k = 0; k < BEAM_N; k++) {
            v[k] = sc[k] + tmrow[k * BEAM_N + l];   // coalesced across l
            mx = fmaxf(mx, v[k]);
        }
        float s = 0.f;
#pragma unroll
        for (int k = 0; k < BEAM_N; k++) s += expf(v[k] - mx);
        float nxt = mx + logf(s) + g_bemit[(size_t)(b * TLEN + t) * BEAM_N + l];
        bool m = (target[b * TLEN + t] != 0);
        __syncthreads();
        if (m) sc[l] = nxt;
        __syncthreads();
    }

    if (l == 0) {
        float num = 0.f;
        for (int i = 0; i < BEAM_N; i++) num += red[i];
        float mx = sc[0];
        for (int i = 1; i < BEAM_N; i++) mx = fmaxf(mx, sc[i]);
        float s = 0.f;
        for (int i = 0; i < BEAM_N; i++) s += expf(sc[i] - mx);
        float den = mx + logf(s);
        losses[b] = -(num - den);
    }
}

// ============================================================================
extern "C" void kernel_launch(void* const* d_in, const int* in_sizes, int n_in,
                              void* d_out, int out_size)
{
    const float* modelout = (const float*)d_in[0];
    const float* W        = (const float*)d_in[1];
    const float* bias     = (const float*)d_in[2];
    const float* E1       = (const float*)d_in[3];
    const float* E2       = (const float*)d_in[4];
    const int*   target   = (const int*)  d_in[5];   // jnp.int64 -> int32 (JAX x64 off)

    float* logits = (float*)d_out;
    float* losses = logits + (size_t)MROWS * VOCAB_N;

    dim3 ggrid(VOCAB_N / 128, MROWS / 128);   // (250, 16)
    gemm_kernel<<<ggrid, 256>>>(modelout, W, bias, logits);
    topk_kernel<<<MROWS, 256>>>(logits, target);
    transmat_kernel<<<BATCH * (TLEN - 1), 256>>>(E1, E2);
    forward_kernel<<<BATCH, 64>>>(logits, target, E1, E2, losses);
}

// round 5
// speedup vs baseline: 1.0038x; 1.0038x over previous
#include <cuda_runtime.h>
#include <math.h>

#define BATCH   4
#define TLEN    512
#define EDIM    1024
#define VOCAB_N 32000
#define BEAM_N  64
#define RANK_N  32
#define MROWS   (BATCH * TLEN)   // 2048

// ---------------- scratch (static device globals; no runtime allocation) ----
__device__ int   g_beams[MROWS * BEAM_N];                       // 512 KB
__device__ float g_bemit[MROWS * BEAM_N];                       // 512 KB
__device__ float g_tm[BATCH * (TLEN - 1) * BEAM_N * BEAM_N];    // 33.5 MB

// ============================================================================
// 1) SGEMM: C[m,n] = sum_k A[m,k] * Bw[n,k] + bias[n]
//    A = modelout (2048 x 1024), Bw = W (32000 x 1024), both K-major (NT gemm)
//    128x128x16 tile, 256 threads, 8x8 register microtile.
// ============================================================================
__global__ void __launch_bounds__(256)
gemm_kernel(const float* __restrict__ A, const float* __restrict__ Bw,
            const float* __restrict__ bias, float* __restrict__ C)
{
    const int BM = 128, BN = 128, BK = 16;
    __shared__ float As[BK][BM];
    __shared__ float Bs[BK][BN];

    int tid  = threadIdx.x;
    int row0 = blockIdx.y * BM;
    int col0 = blockIdx.x * BN;
    int tx = tid & 15;        // 0..15 -> N microtiles
    int ty = tid >> 4;        // 0..15 -> M microtiles

    float acc[8][8];
#pragma unroll
    for (int i = 0; i < 8; i++)
#pragma unroll
        for (int j = 0; j < 8; j++) acc[i][j] = 0.f;

    for (int k0 = 0; k0 < EDIM; k0 += BK) {
        // load 128x16 of A and Bw, transposed into smem: 512 float4 each, 2/thread
#pragma unroll
        for (int i = 0; i < 2; i++) {
            int l  = tid + i * 256;
            int r  = l >> 2;     // row within tile (0..127)
            int c4 = l & 3;      // float4 within the 16-wide row
            float4 va = *(const float4*)(&A [(size_t)(row0 + r) * EDIM + k0 + c4 * 4]);
            As[c4 * 4 + 0][r] = va.x; As[c4 * 4 + 1][r] = va.y;
            As[c4 * 4 + 2][r] = va.z; As[c4 * 4 + 3][r] = va.w;
            float4 vb = *(const float4*)(&Bw[(size_t)(col0 + r) * EDIM + k0 + c4 * 4]);
            Bs[c4 * 4 + 0][r] = vb.x; Bs[c4 * 4 + 1][r] = vb.y;
            Bs[c4 * 4 + 2][r] = vb.z; Bs[c4 * 4 + 3][r] = vb.w;
        }
        __syncthreads();

#pragma unroll
        for (int k = 0; k < BK; k++) {
            float ra[8], rb[8];
            float4 a0 = *(const float4*)(&As[k][ty * 8]);
            float4 a1 = *(const float4*)(&As[k][ty * 8 + 4]);
            ra[0]=a0.x; ra[1]=a0.y; ra[2]=a0.z; ra[3]=a0.w;
            ra[4]=a1.x; ra[5]=a1.y; ra[6]=a1.z; ra[7]=a1.w;
            float4 b0 = *(const float4*)(&Bs[k][tx * 8]);
            float4 b1 = *(const float4*)(&Bs[k][tx * 8 + 4]);
            rb[0]=b0.x; rb[1]=b0.y; rb[2]=b0.z; rb[3]=b0.w;
            rb[4]=b1.x; rb[5]=b1.y; rb[6]=b1.z; rb[7]=b1.w;
#pragma unroll
            for (int i = 0; i < 8; i++)
#pragma unroll
                for (int j = 0; j < 8; j++)
                    acc[i][j] += ra[i] * rb[j];
        }
        __syncthreads();
    }

#pragma unroll
    for (int i = 0; i < 8; i++) {
        size_t rbase = (size_t)(row0 + ty * 8 + i) * VOCAB_N + col0 + tx * 8;
#pragma unroll
        for (int j = 0; j < 8; j++)
            C[rbase + j] = acc[i][j] + bias[col0 + tx * 8 + j];
    }
}

// ============================================================================
// 2) Exact top-64 per row via 4-pass radix select on order-preserving keys.
//    Target index forced to key=0xFFFFFFFF (matches "set to +inf" semantics).
//    Beam ORDER is irrelevant downstream (logsumexp is permutation-invariant).
// ============================================================================
__device__ __forceinline__ unsigned f2key(float x)
{
    unsigned u = __float_as_uint(x);
    return (u & 0x80000000u) ? ~u : (u | 0x80000000u);
}

__global__ void __launch_bounds__(256)
topk_kernel(const float* __restrict__ logits, const int* __restrict__ target)
{
    int row = blockIdx.x;
    const float* lrow = logits + (size_t)row * VOCAB_N;
    int tgt = target[row];
    int tid = threadIdx.x;

    __shared__ unsigned hist[256];
    __shared__ unsigned s_pref;
    __shared__ int s_want;
    __shared__ int cnt_gt, cnt_eq;

    if (tid == 0) { s_pref = 0u; s_want = BEAM_N; }
    __syncthreads();

    for (int pass = 0; pass < 4; pass++) {
        hist[tid] = 0;
        __syncthreads();
        unsigned pref = s_pref;
        int shift = 24 - pass * 8;
        for (int i = tid; i < VOCAB_N; i += 256) {
            unsigned key = (i == tgt) ? 0xFFFFFFFFu : f2key(lrow[i]);
            bool part = (pass == 0) || ((key >> (shift + 8)) == pref);
            if (part) atomicAdd(&hist[(key >> shift) & 0xFFu], 1u);
        }
        __syncthreads();
        if (tid == 0) {
            int want = s_want;
            unsigned cum = 0;
            for (int b = 255; b >= 0; b--) {
                unsigned c = hist[b];
                if (cum + c >= (unsigned)want) {
                    s_pref = (pref << 8) | (unsigned)b;
                    s_want = want - (int)cum;
                    break;
                }
                cum += c;
            }
        }
        __syncthreads();
    }

    unsigned thresh = s_pref;   // exact 64th-largest key
    int want = s_want;          // how many of the ==thresh keys to take
    int nGT  = BEAM_N - want;
    if (tid == 0) { cnt_gt = 0; cnt_eq = 0; }
    __syncthreads();

    for (int i = tid; i < VOCAB_N; i += 256) {
        unsigned key = (i == tgt) ? 0xFFFFFFFFu : f2key(lrow[i]);
        if (key > thresh) {
            int p = atomicAdd(&cnt_gt, 1);
            g_beams[row * BEAM_N + p] = i;
        } else if (key == thresh) {
            int p = atomicAdd(&cnt_eq, 1);
            if (p < want) g_beams[row * BEAM_N + nGT + p] = i;
        }
    }
    __syncthreads();

    if (tid < BEAM_N) {
        int idx = g_beams[row * BEAM_N + tid];
        g_bemit[row * BEAM_N + tid] = lrow[idx];  // original logit (not +inf)
    }
}

// ============================================================================
// 3) trans_mat[b,t,k,l] = dot(E1[beam[b,t,k]], E2[beam[b,t+1,l]])  (rank 32)
// ============================================================================
__global__ void __launch_bounds__(256)
transmat_kernel(const float* __restrict__ E1, const float* __restrict__ E2)
{
    int bt = blockIdx.x;           // 0 .. BATCH*(TLEN-1)-1
    int b  = bt / (TLEN - 1);
    int t  = bt % (TLEN - 1);
    int tid = threadIdx.x;

    __shared__ float s1[BEAM_N][RANK_N + 1];
    __shared__ float s2[BEAM_N][RANK_N + 1];

    const int* bm0 = g_beams + (size_t)(b * TLEN + t) * BEAM_N;
    const int* bm1 = bm0 + BEAM_N;

    for (int i = tid; i < BEAM_N * RANK_N; i += 256) {
        int k = i >> 5, r = i & 31;
        s1[k][r] = E1[(size_t)bm0[k] * RANK_N + r];
        s2[k][r] = E2[(size_t)bm1[k] * RANK_N + r];
    }
    __syncthreads();

    float* out = g_tm + (size_t)bt * (BEAM_N * BEAM_N);
    for (int o = tid; o < BEAM_N * BEAM_N; o += 256) {
        int kk = o >> 6, ll = o & 63;
        float acc = 0.f;
#pragma unroll
        for (int r = 0; r < RANK_N; r++) acc += s1[kk][r] * s2[ll][r];
        out[o] = acc;
    }
}

// ============================================================================
// 4) Forward recursion + numerator + final loss. One block per batch element.
// ============================================================================
__global__ void __launch_bounds__(64)
forward_kernel(const float* __restrict__ logits, const int* __restrict__ target,
               const float* __restrict__ E1, const float* __restrict__ E2,
               float* __restrict__ losses)
{
    int b = blockIdx.x;
    int l = threadIdx.x;
    __shared__ float sc[BEAM_N];
    __shared__ float red[BEAM_N];

    // ---- numerator: sum_t mask[t]*(emit[t] + (t>0 ? trans[t] : 0)) ----
    float np = 0.f;
    for (int t = l; t < TLEN; t += BEAM_N) {
        int tg = target[b * TLEN + t];
        if (tg != 0) {
            float e = logits[(size_t)(b * TLEN + t) * VOCAB_N + tg];
            float tr = 0.f;
            if (t > 0) {
                int tp = target[b * TLEN + t - 1];
#pragma unroll
                for (int r = 0; r < RANK_N; r++)
                    tr += E1[(size_t)tp * RANK_N + r] * E2[(size_t)tg * RANK_N + r];
            }
            np += e + tr;
        }
    }
    red[l] = np;
    sc[l]  = g_bemit[(size_t)(b * TLEN) * BEAM_N + l];   // score0 = beam_emit[:,0]
    __syncthreads();

    // ---- sequential scan over T ----
    for (int t = 1; t < TLEN; t++) {
        const float* tmrow = g_tm + (size_t)(b * (TLEN - 1) + t - 1) * (BEAM_N * BEAM_N);
        float v[BEAM_N];
        float mx = -3.4e38f;
#pragma unroll
        for (int k = 0; k < BEAM_N; k++) {
            v[k] = sc[k] + tmrow[k * BEAM_N + l];   // coalesced across l
            mx = fmaxf(mx, v[k]);
        }
        float s = 0.f;
#pragma unroll
        for (int k = 0; k < BEAM_N; k++) s += expf(v[k] - mx);
        float nxt = mx + logf(s) + g_bemit[(size_t)(b * TLEN + t) * BEAM_N + l];
        bool m = (target[b * TLEN + t] != 0);
        __syncthreads();
        if (m) sc[l] = nxt;
        __syncthreads();
    }

    if (l == 0) {
        float num = 0.f;
        for (int i = 0; i < BEAM_N; i++) num += red[i];
        float mx = sc[0];
        for (int i = 1; i < BEAM_N; i++) mx = fmaxf(mx, sc[i]);
        float s = 0.f;
        for (int i = 0; i < BEAM_N; i++) s += expf(sc[i] - mx);
        float den = mx + logf(s);
        losses[b] = -(num - den);
    }
}

// ============================================================================
extern "C" void kernel_launch(void* const* d_in, const int* in_sizes, int n_in,
                              void* d_out, int out_size)
{
    const float* modelout = (const float*)d_in[0];
    const float* W        = (const float*)d_in[1];
    const float* bias     = (const float*)d_in[2];
    const float* E1       = (const float*)d_in[3];
    const float* E2       = (const float*)d_in[4];
    const int*   target   = (const int*)  d_in[5];   // jnp.int64 -> int32 (JAX x64 off)

    float* logits = (float*)d_out;
    float* losses = logits + (size_t)MROWS * VOCAB_N;

    dim3 ggrid(VOCAB_N / 128, MROWS / 128);   // (250, 16)
    gemm_kernel<<<ggrid, 256>>>(modelout, W, bias, logits);
    topk_kernel<<<MROWS, 256>>>(logits, target);
    transmat_kernel<<<BATCH * (TLEN - 1), 256>>>(E1, E2);
    forward_kernel<<<BATCH, 64>>>(logits, target, E1, E2, losses);
}

// round 10
// speedup vs baseline: 1.6615x; 1.6552x over previous
#include <cuda_runtime.h>
#include <cuda_bf16.h>
#include <math.h>
#include <stdint.h>

#define BATCH   4
#define TLEN    512
#define EDIM    1024
#define VOCAB_N 32000
#define BEAM_N  64
#define RANK_N  32
#define MROWS   (BATCH * TLEN)

__device__ __align__(16) __nv_bfloat16 g_Ahi[MROWS * EDIM];
__device__ __align__(16) __nv_bfloat16 g_Alo[MROWS * EDIM];
__device__ __align__(16) __nv_bfloat16 g_Bhi[VOCAB_N * EDIM];
__device__ __align__(16) __nv_bfloat16 g_Blo[VOCAB_N * EDIM];
__device__ int   g_beams[MROWS * BEAM_N];
__device__ float g_bemit[MROWS * BEAM_N];
__device__ float g_tm[BATCH * (TLEN - 1) * BEAM_N * BEAM_N];

// ---------------------------------------------------------------- helpers --
__device__ __forceinline__ uint32_t s2u(const void* p) {
    uint32_t a;
    asm("{ .reg .u64 t; cvta.to.shared.u64 t, %1; cvt.u32.u64 %0, t; }" : "=r"(a) : "l"(p));
    return a;
}
__device__ __forceinline__ void cpasync16(uint32_t s, const void* g) {
    asm volatile("cp.async.cg.shared.global [%0], [%1], 16;" :: "r"(s), "l"(g) : "memory");
}
__device__ __forceinline__ void ldm4(uint32_t* f, uint32_t addr) {
    asm volatile("ldmatrix.sync.aligned.m8n8.x4.shared.b16 {%0,%1,%2,%3}, [%4];"
        : "=r"(f[0]), "=r"(f[1]), "=r"(f[2]), "=r"(f[3]) : "r"(addr));
}
__device__ __forceinline__ void mma16816(float* d, const uint32_t* a,
                                         uint32_t b0, uint32_t b1) {
    asm volatile("mma.sync.aligned.m16n8k16.row.col.f32.bf16.bf16.f32 "
        "{%0,%1,%2,%3}, {%4,%5,%6,%7}, {%8,%9}, {%0,%1,%2,%3};"
        : "+f"(d[0]), "+f"(d[1]), "+f"(d[2]), "+f"(d[3])
        : "r"(a[0]), "r"(a[1]), "r"(a[2]), "r"(a[3]), "r"(b0), "r"(b1));
}

// ============================ 0) fp32 -> bf16 hi/lo split ===================
__device__ __forceinline__ void split4(float4 v, uint2& uh, uint2& ul) {
    __nv_bfloat16 h0 = __float2bfloat16(v.x), h1 = __float2bfloat16(v.y);
    __nv_bfloat16 h2 = __float2bfloat16(v.z), h3 = __float2bfloat16(v.w);
    __nv_bfloat16 l0 = __float2bfloat16(v.x - __bfloat162float(h0));
    __nv_bfloat16 l1 = __float2bfloat16(v.y - __bfloat162float(h1));
    __nv_bfloat16 l2 = __float2bfloat16(v.z - __bfloat162float(h2));
    __nv_bfloat16 l3 = __float2bfloat16(v.w - __bfloat162float(h3));
    uh.x = ((unsigned)__bfloat16_as_ushort(h1) << 16) | __bfloat16_as_ushort(h0);
    uh.y = ((unsigned)__bfloat16_as_ushort(h3) << 16) | __bfloat16_as_ushort(h2);
    ul.x = ((unsigned)__bfloat16_as_ushort(l1) << 16) | __bfloat16_as_ushort(l0);
    ul.y = ((unsigned)__bfloat16_as_ushort(l3) << 16) | __bfloat16_as_ushort(l2);
}
__global__ void __launch_bounds__(256) convertA(const float4* __restrict__ src) {
    int i = blockIdx.x * 256 + threadIdx.x;
    uint2 uh, ul; split4(src[i], uh, ul);
    ((uint2*)g_Ahi)[i] = uh; ((uint2*)g_Alo)[i] = ul;
}
__global__ void __launch_bounds__(256) convertB(const float4* __restrict__ src) {
    int i = blockIdx.x * 256 + threadIdx.x;
    uint2 uh, ul; split4(src[i], uh, ul);
    ((uint2*)g_Bhi)[i] = uh; ((uint2*)g_Blo)[i] = ul;
}

// ============================ 1) mma.sync bf16 GEMM =========================
// C[2048,32000] = Ahi*Bhi^T + Ahi*Blo^T + Alo*Bhi^T + bias
// CTA 128x128, BK=32, 3-stage cp.async pipeline, warp tile 32x64.
#define BKI 32
#define KITERS (EDIM / BKI)              // 32
#define ROW_B 80                          // padded row: 40 bf16 = 80 bytes
#define MAT_BYTES (128 * ROW_B)           // 10240
#define STAGE_BYTES (4 * MAT_BYTES)       // 40960: Ahi|Alo|Bhi|Blo
#define NSTAGE 3
#define GEMM_SMEM (NSTAGE * STAGE_BYTES)  // 122880

__device__ __forceinline__ void load_stage(uint32_t sbase, int buf, int it,
                                           int tid, int row0, int col0) {
    uint32_t st = sbase + buf * STAGE_BYTES;
    int k0 = it * BKI;
#pragma unroll
    for (int j = 0; j < 8; j++) {
        int cid = tid + j * 256;          // 2048 16B-chunks per stage
        int mat = cid >> 9;               // 0:Ahi 1:Alo 2:Bhi 3:Blo
        int rc  = cid & 511;
        int r = rc >> 2, c = rc & 3;      // 128 rows x 4 chunks
        const __nv_bfloat16* gp;
        if (mat == 0)      gp = g_Ahi + (size_t)(row0 + r) * EDIM + k0 + c * 8;
        else if (mat == 1) gp = g_Alo + (size_t)(row0 + r) * EDIM + k0 + c * 8;
        else if (mat == 2) gp = g_Bhi + (size_t)(col0 + r) * EDIM + k0 + c * 8;
        else               gp = g_Blo + (size_t)(col0 + r) * EDIM + k0 + c * 8;
        cpasync16(st + (uint32_t)(mat * MAT_BYTES + r * ROW_B + c * 16), gp);
    }
    asm volatile("cp.async.commit_group;" ::: "memory");
}

__global__ void __launch_bounds__(256, 1)
gemm_mma(const float* __restrict__ bias, float* __restrict__ C)
{
    extern __shared__ char smem[];
    uint32_t sbase = s2u(smem);
    int tid = threadIdx.x, lane = tid & 31, wid = tid >> 5;

    // grid swizzle: groups of 10 col-blocks x 16 row-blocks for L2 reuse
    int bid = blockIdx.x;
    int grp = bid / 160, w = bid % 160;
    int row0 = (w & 15) * 128;
    int col0 = (grp * 10 + (w >> 4)) * 128;

    int warp_m = wid & 3;                 // 4 -> rows 32 each
    int warp_n = wid >> 2;                // 2 -> cols 64 each

    float acc[2][8][4];
#pragma unroll
    for (int mi = 0; mi < 2; mi++)
#pragma unroll
        for (int ni = 0; ni < 8; ni++)
#pragma unroll
            for (int q = 0; q < 4; q++) acc[mi][ni][q] = 0.f;

    load_stage(sbase, 0, 0, tid, row0, col0);
    load_stage(sbase, 1, 1, tid, row0, col0);

    // per-lane ldmatrix base offsets (bytes within a matrix)
    uint32_t aoff = (uint32_t)(warp_m * 32 + (lane & 15)) * ROW_B + ((lane >> 4) * 16);
    uint32_t boff = (uint32_t)(warp_n * 64 + (lane & 7) + ((lane >> 4) << 3)) * ROW_B
                  + (((lane >> 3) & 1) * 16);

    for (int it = 0; it < KITERS; it++) {
        if (it < KITERS - 2) asm volatile("cp.async.wait_group 1;" ::: "memory");
        else                 asm volatile("cp.async.wait_group 0;" ::: "memory");
        __syncthreads();
        if (it + 2 < KITERS) load_stage(sbase, (it + 2) % NSTAGE, it + 2, tid, row0, col0);

        uint32_t st = sbase + (uint32_t)((it % NSTAGE) * STAGE_BYTES);
#pragma unroll
        for (int ks = 0; ks < 2; ks++) {
            uint32_t kb = ks * 32;        // 16 bf16 = 32 bytes
            uint32_t ahi[2][4], alo[2][4], bhi[4][4], blo[4][4];
#pragma unroll
            for (int mi = 0; mi < 2; mi++) {
                ldm4(ahi[mi], st + 0 * MAT_BYTES + mi * (16 * ROW_B) + aoff + kb);
                ldm4(alo[mi], st + 1 * MAT_BYTES + mi * (16 * ROW_B) + aoff + kb);
            }
#pragma unroll
            for (int nt = 0; nt < 4; nt++) {
                ldm4(bhi[nt], st + 2 * MAT_BYTES + nt * (16 * ROW_B) + boff + kb);
                ldm4(blo[nt], st + 3 * MAT_BYTES + nt * (16 * ROW_B) + boff + kb);
            }
#pragma unroll
            for (int mi = 0; mi < 2; mi++)
#pragma unroll
                for (int ni = 0; ni < 8; ni++) {
                    int nt = ni >> 1, p = (ni & 1) * 2;
                    mma16816(acc[mi][ni], ahi[mi], bhi[nt][p], bhi[nt][p + 1]);
                    mma16816(acc[mi][ni], ahi[mi], blo[nt][p], blo[nt][p + 1]);
                    mma16816(acc[mi][ni], alo[mi], bhi[nt][p], bhi[nt][p + 1]);
                }
        }
    }

    // epilogue: D[g][ti*2], D[g+8][ti*2] per mma tile, + bias
    int ti2 = (lane & 3) * 2, g8 = lane >> 2;
#pragma unroll
    for (int ni = 0; ni < 8; ni++) {
        int colg = col0 + warp_n * 64 + ni * 8 + ti2;
        float b0 = bias[colg], b1 = bias[colg + 1];
#pragma unroll
        for (int mi = 0; mi < 2; mi++) {
            int rowg = row0 + warp_m * 32 + mi * 16 + g8;
            float2 v0 = { acc[mi][ni][0] + b0, acc[mi][ni][1] + b1 };
            float2 v1 = { acc[mi][ni][2] + b0, acc[mi][ni][3] + b1 };
            *(float2*)(C + (size_t)rowg * VOCAB_N + colg) = v0;
            *(float2*)(C + (size_t)(rowg + 8) * VOCAB_N + colg) = v1;
        }
    }
}

// ============================ 2) top-64 radix select ========================
__device__ __forceinline__ unsigned f2key(float x) {
    unsigned u = __float_as_uint(x);
    return (u & 0x80000000u) ? ~u : (u | 0x80000000u);
}
__global__ void __launch_bounds__(256)
topk_kernel(const float* __restrict__ logits, const int* __restrict__ target)
{
    int row = blockIdx.x;
    const float* lrow = logits + (size_t)row * VOCAB_N;
    int tgt = target[row];
    int tid = threadIdx.x;
    __shared__ unsigned hist[256];
    __shared__ unsigned s_pref;
    __shared__ int s_want, cnt_gt, cnt_eq;

    if (tid == 0) { s_pref = 0u; s_want = BEAM_N; }
    __syncthreads();
    for (int pass = 0; pass < 4; pass++) {
        hist[tid] = 0;
        __syncthreads();
        unsigned pref = s_pref;
        int shift = 24 - pass * 8;
        for (int i = tid; i < VOCAB_N; i += 256) {
            unsigned key = (i == tgt) ? 0xFFFFFFFFu : f2key(lrow[i]);
            bool part = (pass == 0) || ((key >> (shift + 8)) == pref);
            if (part) atomicAdd(&hist[(key >> shift) & 0xFFu], 1u);
        }
        __syncthreads();
        if (tid == 0) {
            int want = s_want;
            unsigned cum = 0;
            for (int b = 255; b >= 0; b--) {
                unsigned c = hist[b];
                if (cum + c >= (unsigned)want) {
                    s_pref = (pref << 8) | (unsigned)b;
                    s_want = want - (int)cum;
                    break;
                }
                cum += c;
            }
        }
        __syncthreads();
    }
    unsigned thresh = s_pref;
    int want = s_want, nGT = BEAM_N - want;
    if (tid == 0) { cnt_gt = 0; cnt_eq = 0; }
    __syncthreads();
    for (int i = tid; i < VOCAB_N; i += 256) {
        unsigned key = (i == tgt) ? 0xFFFFFFFFu : f2key(lrow[i]);
        if (key > thresh) {
            int p = atomicAdd(&cnt_gt, 1);
            g_beams[row * BEAM_N + p] = i;
        } else if (key == thresh) {
            int p = atomicAdd(&cnt_eq, 1);
            if (p < want) g_beams[row * BEAM_N + nGT + p] = i;
        }
    }
    __syncthreads();
    if (tid < BEAM_N) {
        int idx = g_beams[row * BEAM_N + tid];
        g_bemit[row * BEAM_N + tid] = lrow[idx];
    }
}

// ============================ 3) trans_mat ==================================
__global__ void __launch_bounds__(256)
transmat_kernel(const float* __restrict__ E1, const float* __restrict__ E2)
{
    int bt = blockIdx.x;
    int b = bt / (TLEN - 1), t = bt % (TLEN - 1);
    int tid = threadIdx.x;
    __shared__ float s1[BEAM_N][RANK_N + 1];
    __shared__ float s2[BEAM_N][RANK_N + 1];
    const int* bm0 = g_beams + (size_t)(b * TLEN + t) * BEAM_N;
    const int* bm1 = bm0 + BEAM_N;
    for (int i = tid; i < BEAM_N * RANK_N; i += 256) {
        int k = i >> 5, r = i & 31;
        s1[k][r] = E1[(size_t)bm0[k] * RANK_N + r];
        s2[k][r] = E2[(size_t)bm1[k] * RANK_N + r];
    }
    __syncthreads();
    float* out = g_tm + (size_t)bt * (BEAM_N * BEAM_N);
    for (int o = tid; o < BEAM_N * BEAM_N; o += 256) {
        int kk = o >> 6, ll = o & 63;
        float acc = 0.f;
#pragma unroll
        for (int r = 0; r < RANK_N; r++) acc += s1[kk][r] * s2[ll][r];
        out[o] = acc;
    }
}

// ============================ 4) forward recursion ==========================
__global__ void __launch_bounds__(64)
forward_kernel(const float* __restrict__ logits, const int* __restrict__ target,
               const float* __restrict__ E1, const float* __restrict__ E2,
               float* __restrict__ losses)
{
    int b = blockIdx.x, l = threadIdx.x;
    __shared__ float sc[BEAM_N];
    __shared__ float red[BEAM_N];
    float np = 0.f;
    for (int t = l; t < TLEN; t += BEAM_N) {
        int tg = target[b * TLEN + t];
        if (tg != 0) {
            float e = logits[(size_t)(b * TLEN + t) * VOCAB_N + tg];
            float tr = 0.f;
            if (t > 0) {
                int tp = target[b * TLEN + t - 1];
#pragma unroll
                for (int r = 0; r < RANK_N; r++)
                    tr += E1[(size_t)tp * RANK_N + r] * E2[(size_t)tg * RANK_N + r];
            }
            np += e + tr;
        }
    }
    red[l] = np;
    sc[l] = g_bemit[(size_t)(b * TLEN) * BEAM_N + l];
    __syncthreads();
    for (int t = 1; t < TLEN; t++) {
        const float* tmrow = g_tm + (size_t)(b * (TLEN - 1) + t - 1) * (BEAM_N * BEAM_N);
        float v[BEAM_N];
        float mx = -3.4e38f;
#pragma unroll
        for (int k = 0; k < BEAM_N; k++) {
            v[k] = sc[k] + tmrow[k * BEAM_N + l];
            mx = fmaxf(mx, v[k]);
        }
        float s = 0.f;
#pragma unroll
        for (int k = 0; k < BEAM_N; k++) s += expf(v[k] - mx);
        float nxt = mx + logf(s) + g_bemit[(size_t)(b * TLEN + t) * BEAM_N + l];
        bool m = (target[b * TLEN + t] != 0);
        __syncthreads();
        if (m) sc[l] = nxt;
        __syncthreads();
    }
    if (l == 0) {
        float num = 0.f;
        for (int i = 0; i < BEAM_N; i++) num += red[i];
        float mx = sc[0];
        for (int i = 1; i < BEAM_N; i++) mx = fmaxf(mx, sc[i]);
        float s = 0.f;
        for (int i = 0; i < BEAM_N; i++) s += expf(sc[i] - mx);
        losses[b] = -(num - (mx + logf(s)));
    }
}

// ============================================================================
extern "C" void kernel_launch(void* const* d_in, const int* in_sizes, int n_in,
                              void* d_out, int out_size)
{
    const float* modelout = (const float*)d_in[0];
    const float* W        = (const float*)d_in[1];
    const float* bias     = (const float*)d_in[2];
    const float* E1       = (const float*)d_in[3];
    const float* E2       = (const float*)d_in[4];
    const int*   target   = (const int*)  d_in[5];

    float* logits = (float*)d_out;
    float* losses = logits + (size_t)MROWS * VOCAB_N;

    cudaFuncSetAttribute(gemm_mma, cudaFuncAttributeMaxDynamicSharedMemorySize, GEMM_SMEM);

    convertA<<<MROWS * EDIM / 1024, 256>>>((const float4*)modelout);
    convertB<<<VOCAB_N * EDIM / 1024, 256>>>((const float4*)W);
    gemm_mma<<<(VOCAB_N / 128) * (MROWS / 128), 256, GEMM_SMEM>>>(bias, logits);
    topk_kernel<<<MROWS, 256>>>(logits, target);
    transmat_kernel<<<BATCH * (TLEN - 1), 256>>>(E1, E2);
    forward_kernel<<<BATCH, 64>>>(logits, target, E1, E2, losses);
}

// round 12
// speedup vs baseline: 2.1794x; 1.3117x over previous
#include <cuda_runtime.h>
#include <cuda_bf16.h>
#include <math.h>
#include <stdint.h>

#define BATCH   4
#define TLEN    512
#define EDIM    1024
#define VOCAB_N 32000
#define BEAM_N  64
#define RANK_N  32
#define MROWS   (BATCH * TLEN)

__device__ __align__(16) __nv_bfloat16 g_Ahi[MROWS * EDIM];
__device__ __align__(16) __nv_bfloat16 g_Alo[MROWS * EDIM];
__device__ __align__(16) __nv_bfloat16 g_Bhi[VOCAB_N * EDIM];
__device__ __align__(16) __nv_bfloat16 g_Blo[VOCAB_N * EDIM];
__device__ int   g_beams[MROWS * BEAM_N];
__device__ float g_bemit[MROWS * BEAM_N];
__device__ float g_tm[BATCH * (TLEN - 1) * BEAM_N * BEAM_N];

// ---------------------------------------------------------------- helpers --
__device__ __forceinline__ uint32_t s2u(const void* p) {
    uint32_t a;
    asm("{ .reg .u64 t; cvta.to.shared.u64 t, %1; cvt.u32.u64 %0, t; }" : "=r"(a) : "l"(p));
    return a;
}
__device__ __forceinline__ void cpasync16(uint32_t s, const void* g) {
    asm volatile("cp.async.cg.shared.global [%0], [%1], 16;" :: "r"(s), "l"(g) : "memory");
}
__device__ __forceinline__ void ldm4(uint32_t* f, uint32_t addr) {
    asm volatile("ldmatrix.sync.aligned.m8n8.x4.shared.b16 {%0,%1,%2,%3}, [%4];"
        : "=r"(f[0]), "=r"(f[1]), "=r"(f[2]), "=r"(f[3]) : "r"(addr));
}
__device__ __forceinline__ void mma16816(float* d, const uint32_t* a,
                                         uint32_t b0, uint32_t b1) {
    asm volatile("mma.sync.aligned.m16n8k16.row.col.f32.bf16.bf16.f32 "
        "{%0,%1,%2,%3}, {%4,%5,%6,%7}, {%8,%9}, {%0,%1,%2,%3};"
        : "+f"(d[0]), "+f"(d[1]), "+f"(d[2]), "+f"(d[3])
        : "r"(a[0]), "r"(a[1]), "r"(a[2]), "r"(a[3]), "r"(b0), "r"(b1));
}

// ============================ 0) fp32 -> bf16 hi/lo split ===================
__device__ __forceinline__ void split4(float4 v, uint2& uh, uint2& ul) {
    __nv_bfloat16 h0 = __float2bfloat16(v.x), h1 = __float2bfloat16(v.y);
    __nv_bfloat16 h2 = __float2bfloat16(v.z), h3 = __float2bfloat16(v.w);
    __nv_bfloat16 l0 = __float2bfloat16(v.x - __bfloat162float(h0));
    __nv_bfloat16 l1 = __float2bfloat16(v.y - __bfloat162float(h1));
    __nv_bfloat16 l2 = __float2bfloat16(v.z - __bfloat162float(h2));
    __nv_bfloat16 l3 = __float2bfloat16(v.w - __bfloat162float(h3));
    uh.x = ((unsigned)__bfloat16_as_ushort(h1) << 16) | __bfloat16_as_ushort(h0);
    uh.y = ((unsigned)__bfloat16_as_ushort(h3) << 16) | __bfloat16_as_ushort(h2);
    ul.x = ((unsigned)__bfloat16_as_ushort(l1) << 16) | __bfloat16_as_ushort(l0);
    ul.y = ((unsigned)__bfloat16_as_ushort(l3) << 16) | __bfloat16_as_ushort(l2);
}
__global__ void __launch_bounds__(256) convertA(const float4* __restrict__ src) {
    int i = blockIdx.x * 256 + threadIdx.x;
    uint2 uh, ul; split4(src[i], uh, ul);
    ((uint2*)g_Ahi)[i] = uh; ((uint2*)g_Alo)[i] = ul;
}
__global__ void __launch_bounds__(256) convertB(const float4* __restrict__ src) {
    int i = blockIdx.x * 256 + threadIdx.x;
    uint2 uh, ul; split4(src[i], uh, ul);
    ((uint2*)g_Bhi)[i] = uh; ((uint2*)g_Blo)[i] = ul;
}

// ============================ 1) mma.sync bf16 GEMM =========================
// C[2048,32000] = Ahi*Bhi^T + Ahi*Blo^T + Alo*Bhi^T + bias
// CTA 128x128, BK=32, 2-stage cp.async pipeline, 2 CTAs/SM, warp tile 32x64.
#define BKI 32
#define KITERS (EDIM / BKI)              // 32
#define ROW_B 80
#define MAT_BYTES (128 * ROW_B)
#define STAGE_BYTES (4 * MAT_BYTES)       // 40960
#define NSTAGE 2
#define GEMM_SMEM (NSTAGE * STAGE_BYTES)  // 81920

__device__ __forceinline__ void load_stage(uint32_t sbase, int buf, int it,
                                           int tid, int row0, int col0) {
    uint32_t st = sbase + buf * STAGE_BYTES;
    int k0 = it * BKI;
#pragma unroll
    for (int j = 0; j < 8; j++) {
        int cid = tid + j * 256;
        int mat = cid >> 9;
        int rc  = cid & 511;
        int r = rc >> 2, c = rc & 3;
        const __nv_bfloat16* gp;
        if (mat == 0)      gp = g_Ahi + (size_t)(row0 + r) * EDIM + k0 + c * 8;
        else if (mat == 1) gp = g_Alo + (size_t)(row0 + r) * EDIM + k0 + c * 8;
        else if (mat == 2) gp = g_Bhi + (size_t)(col0 + r) * EDIM + k0 + c * 8;
        else               gp = g_Blo + (size_t)(col0 + r) * EDIM + k0 + c * 8;
        cpasync16(st + (uint32_t)(mat * MAT_BYTES + r * ROW_B + c * 16), gp);
    }
    asm volatile("cp.async.commit_group;" ::: "memory");
}

__global__ void __launch_bounds__(256, 2)
gemm_mma(const float* __restrict__ bias, float* __restrict__ C)
{
    extern __shared__ char smem[];
    uint32_t sbase = s2u(smem);
    int tid = threadIdx.x, lane = tid & 31, wid = tid >> 5;

    int bid = blockIdx.x;
    int grp = bid / 160, w = bid % 160;
    int row0 = (w & 15) * 128;
    int col0 = (grp * 10 + (w >> 4)) * 128;

    int warp_m = wid & 3;
    int warp_n = wid >> 2;

    float acc[2][8][4];
#pragma unroll
    for (int mi = 0; mi < 2; mi++)
#pragma unroll
        for (int ni = 0; ni < 8; ni++)
#pragma unroll
            for (int q = 0; q < 4; q++) acc[mi][ni][q] = 0.f;

    load_stage(sbase, 0, 0, tid, row0, col0);
    load_stage(sbase, 1, 1, tid, row0, col0);

    uint32_t aoff = (uint32_t)(warp_m * 32 + (lane & 15)) * ROW_B + ((lane >> 4) * 16);
    uint32_t boff = (uint32_t)(warp_n * 64 + (lane & 7) + ((lane >> 4) << 3)) * ROW_B
                  + (((lane >> 3) & 1) * 16);

    for (int it = 0; it < KITERS; it++) {
        if (it < KITERS - 1) asm volatile("cp.async.wait_group 1;" ::: "memory");
        else                 asm volatile("cp.async.wait_group 0;" ::: "memory");
        __syncthreads();

        uint32_t st = sbase + (uint32_t)((it & 1) * STAGE_BYTES);
#pragma unroll
        for (int ks = 0; ks < 2; ks++) {
            uint32_t kb = ks * 32;
            uint32_t ahi[2][4], alo[2][4];
#pragma unroll
            for (int mi = 0; mi < 2; mi++) {
                ldm4(ahi[mi], st + 0 * MAT_BYTES + mi * (16 * ROW_B) + aoff + kb);
                ldm4(alo[mi], st + 1 * MAT_BYTES + mi * (16 * ROW_B) + aoff + kb);
            }
#pragma unroll
            for (int nt = 0; nt < 4; nt++) {
                uint32_t bh[4], bl[4];
                ldm4(bh, st + 2 * MAT_BYTES + nt * (16 * ROW_B) + boff + kb);
                ldm4(bl, st + 3 * MAT_BYTES + nt * (16 * ROW_B) + boff + kb);
#pragma unroll
                for (int mi = 0; mi < 2; mi++) {
                    mma16816(acc[mi][nt*2+0], ahi[mi], bh[0], bh[1]);
                    mma16816(acc[mi][nt*2+1], ahi[mi], bh[2], bh[3]);
                    mma16816(acc[mi][nt*2+0], ahi[mi], bl[0], bl[1]);
                    mma16816(acc[mi][nt*2+1], ahi[mi], bl[2], bl[3]);
                    mma16816(acc[mi][nt*2+0], alo[mi], bh[0], bh[1]);
                    mma16816(acc[mi][nt*2+1], alo[mi], bh[2], bh[3]);
                }
            }
        }
        __syncthreads();
        if (it + 2 < KITERS) load_stage(sbase, it & 1, it + 2, tid, row0, col0);
    }

    int ti2 = (lane & 3) * 2, g8 = lane >> 2;
#pragma unroll
    for (int ni = 0; ni < 8; ni++) {
        int colg = col0 + warp_n * 64 + ni * 8 + ti2;
        float b0 = bias[colg], b1 = bias[colg + 1];
#pragma unroll
        for (int mi = 0; mi < 2; mi++) {
            int rowg = row0 + warp_m * 32 + mi * 16 + g8;
            float2 v0 = { acc[mi][ni][0] + b0, acc[mi][ni][1] + b1 };
            float2 v1 = { acc[mi][ni][2] + b0, acc[mi][ni][3] + b1 };
            *(float2*)(C + (size_t)rowg * VOCAB_N + colg) = v0;
            *(float2*)(C + (size_t)(rowg + 8) * VOCAB_N + colg) = v1;
        }
    }
}

// ============================ 2) top-64: 2-pass select ======================
// Pass 1: 2048-bin histogram of top-11 key bits (float4 loads).
// Pass 2: keys in higher bins -> direct out; boundary bin -> smem candidates;
//         exact finish via 3x7-bit radix on low 21 bits over the candidates.
#define TK_CAP 8192
#define TK_SMEM (2048 * 4 + TK_CAP * 8)   // 73728 bytes

__device__ __forceinline__ unsigned f2key(float x) {
    unsigned u = __float_as_uint(x);
    return (u & 0x80000000u) ? ~u : (u | 0x80000000u);
}

__global__ void __launch_bounds__(256)
topk_kernel(const float* __restrict__ logits, const int* __restrict__ target)
{
    extern __shared__ int tksh[];
    int* hist = tksh;                         // 2048 ints
    unsigned* ck = (unsigned*)(tksh + 2048);  // TK_CAP keys
    int* ci = (int*)(ck + TK_CAP);            // TK_CAP idxs

    __shared__ int s_bin, s_want, s_slot, s_pref, s_want2, cnt_eq, cnt_eq2;

    int row = blockIdx.x;
    const float* lrow = logits + (size_t)row * VOCAB_N;
    const float4* l4 = (const float4*)lrow;
    int tgt = target[row];
    int tid = threadIdx.x;

    for (int i = tid; i < 2048; i += 256) hist[i] = 0;
    __syncthreads();

    // ---- pass 1: histogram of key>>21 ----
    for (int i = tid; i < VOCAB_N / 4; i += 256) {
        float4 v = l4[i];
        atomicAdd(&hist[f2key(v.x) >> 21], 1);
        atomicAdd(&hist[f2key(v.y) >> 21], 1);
        atomicAdd(&hist[f2key(v.z) >> 21], 1);
        atomicAdd(&hist[f2key(v.w) >> 21], 1);
    }
    __syncthreads();
    if (tid == 0) {
        // replace target's natural key with forced max key
        atomicAdd(&hist[f2key(lrow[tgt]) >> 21], -1);
        atomicAdd(&hist[2047], 1);
        int cum = 0, b;
        for (b = 2047; b >= 0; b--) {
            int c = hist[b];
            if (cum + c >= BEAM_N) break;
            cum += c;
        }
        s_bin = b; s_want = BEAM_N - cum; s_slot = 0; cnt_eq = 0;
    }
    __syncthreads();
    int bsel = s_bin;

    // ---- pass 2: direct-out for >bin, candidates for ==bin ----
    for (int i = tid; i < VOCAB_N / 4; i += 256) {
        float4 v = l4[i];
        float vv[4] = { v.x, v.y, v.z, v.w };
#pragma unroll
        for (int j = 0; j < 4; j++) {
            int idx = i * 4 + j;
            unsigned key = (idx == tgt) ? 0xFFFFFFFFu : f2key(vv[j]);
            int bin = (int)(key >> 21);
            if (bin > bsel) {
                int p = atomicAdd(&s_slot, 1);
                g_beams[row * BEAM_N + p] = idx;
            } else if (bin == bsel) {
                int p = atomicAdd(&cnt_eq, 1);
                if (p < TK_CAP) { ck[p] = key; ci[p] = idx; }
            }
        }
    }
    __syncthreads();
    int ncand = min(cnt_eq, TK_CAP);

    // ---- exact select of top-s_want among candidates (low 21 bits) ----
    if (tid == 0) { s_pref = 0; s_want2 = s_want; }
    __syncthreads();
#pragma unroll
    for (int pass = 0; pass < 3; pass++) {
        int shift = 14 - pass * 7;
        for (int i = tid; i < 128; i += 256) hist[i] = 0;
        __syncthreads();
        int pref = s_pref;
        for (int j = tid; j < ncand; j += 256) {
            unsigned low = ck[j] & 0x1FFFFFu;
            if ((int)(low >> (shift + 7)) == pref)
                atomicAdd(&hist[(low >> shift) & 127], 1);
        }
        __syncthreads();
        if (tid == 0) {
            int want = s_want2, cum = 0, b;
            for (b = 127; b >= 0; b--) {
                int c = hist[b];
                if (cum + c >= want) break;
                cum += c;
            }
            s_pref = (pref << 7) | b;
            s_want2 = want - cum;
        }
        __syncthreads();
    }
    unsigned thresh = (unsigned)s_pref;   // exact low-21 threshold
    if (tid == 0) cnt_eq2 = 0;
    __syncthreads();
    int wantEq = s_want2;
    for (int j = tid; j < ncand; j += 256) {
        unsigned low = ck[j] & 0x1FFFFFu;
        if (low > thresh) {
            int p = atomicAdd(&s_slot, 1);
            g_beams[row * BEAM_N + p] = ci[j];
        } else if (low == thresh) {
            int p = atomicAdd(&cnt_eq2, 1);
            if (p < wantEq) {
                int q = atomicAdd(&s_slot, 1);
                g_beams[row * BEAM_N + q] = ci[j];
            }
        }
    }
    __syncthreads();

    if (tid < BEAM_N) {
        int idx = g_beams[row * BEAM_N + tid];
        g_bemit[row * BEAM_N + tid] = lrow[idx];
    }
}

// ============================ 3) trans_mat ==================================
__global__ void __launch_bounds__(256)
transmat_kernel(const float* __restrict__ E1, const float* __restrict__ E2)
{
    int bt = blockIdx.x;
    int b = bt / (TLEN - 1), t = bt % (TLEN - 1);
    int tid = threadIdx.x;
    __shared__ float s1[BEAM_N][RANK_N + 1];
    __shared__ float s2[BEAM_N][RANK_N + 1];
    const int* bm0 = g_beams + (size_t)(b * TLEN + t) * BEAM_N;
    const int* bm1 = bm0 + BEAM_N;
    for (int i = tid; i < BEAM_N * RANK_N; i += 256) {
        int k = i >> 5, r = i & 31;
        s1[k][r] = E1[(size_t)bm0[k] * RANK_N + r];
        s2[k][r] = E2[(size_t)bm1[k] * RANK_N + r];
    }
    __syncthreads();
    float* out = g_tm + (size_t)bt * (BEAM_N * BEAM_N);
    for (int o = tid; o < BEAM_N * BEAM_N; o += 256) {
        int kk = o >> 6, ll = o & 63;
        float acc = 0.f;
#pragma unroll
        for (int r = 0; r < RANK_N; r++) acc += s1[kk][r] * s2[ll][r];
        out[o] = acc;
    }
}

// ============================ 4) forward recursion ==========================
__global__ void __launch_bounds__(64)
forward_kernel(const float* __restrict__ logits, const int* __restrict__ target,
               const float* __restrict__ E1, const float* __restrict__ E2,
               float* __restrict__ losses)
{
    int b = blockIdx.x, l = threadIdx.x;
    __shared__ float sc[BEAM_N];
    __shared__ float red[BEAM_N];
    float np = 0.f;
    for (int t = l; t < TLEN; t += BEAM_N) {
        int tg = target[b * TLEN + t];
        if (tg != 0) {
            float e = logits[(size_t)(b * TLEN + t) * VOCAB_N + tg];
            float tr = 0.f;
            if (t > 0) {
                int tp = target[b * TLEN + t - 1];
#pragma unroll
                for (int r = 0; r < RANK_N; r++)
                    tr += E1[(size_t)tp * RANK_N + r] * E2[(size_t)tg * RANK_N + r];
            }
            np += e + tr;
        }
    }
    red[l] = np;
    sc[l] = g_bemit[(size_t)(b * TLEN) * BEAM_N + l];
    __syncthreads();
    for (int t = 1; t < TLEN; t++) {
        const float* tmrow = g_tm + (size_t)(b * (TLEN - 1) + t - 1) * (BEAM_N * BEAM_N);
        float v[BEAM_N];
        float mx = -3.4e38f;
#pragma unroll
        for (int k = 0; k < BEAM_N; k++) {
            v[k] = sc[k] + tmrow[k * BEAM_N + l];
            mx = fmaxf(mx, v[k]);
        }
        float s = 0.f;
#pragma unroll
        for (int k = 0; k < BEAM_N; k++) s += expf(v[k] - mx);
        float nxt = mx + logf(s) + g_bemit[(size_t)(b * TLEN + t) * BEAM_N + l];
        bool m = (target[b * TLEN + t] != 0);
        __syncthreads();
        if (m) sc[l] = nxt;
        __syncthreads();
    }
    if (l == 0) {
        float num = 0.f;
        for (int i = 0; i < BEAM_N; i++) num += red[i];
        float mx = sc[0];
        for (int i = 1; i < BEAM_N; i++) mx = fmaxf(mx, sc[i]);
        float s = 0.f;
        for (int i = 0; i < BEAM_N; i++) s += expf(sc[i] - mx);
        losses[b] = -(num - (mx + logf(s)));
    }
}

// ============================================================================
extern "C" void kernel_launch(void* const* d_in, const int* in_sizes, int n_in,
                              void* d_out, int out_size)
{
    const float* modelout = (const float*)d_in[0];
    const float* W        = (const float*)d_in[1];
    const float* bias     = (const float*)d_in[2];
    const float* E1       = (const float*)d_in[3];
    const float* E2       = (const float*)d_in[4];
    const int*   target   = (const int*)  d_in[5];

    float* logits = (float*)d_out;
    float* losses = logits + (size_t)MROWS * VOCAB_N;

    cudaFuncSetAttribute(gemm_mma, cudaFuncAttributeMaxDynamicSharedMemorySize, GEMM_SMEM);
    cudaFuncSetAttribute(topk_kernel, cudaFuncAttributeMaxDynamicSharedMemorySize, TK_SMEM);

    convertA<<<MROWS * EDIM / 1024, 256>>>((const float4*)modelout);
    convertB<<<VOCAB_N * EDIM / 1024, 256>>>((const float4*)W);
    gemm_mma<<<(VOCAB_N / 128) * (MROWS / 128), 256, GEMM_SMEM>>>(bias, logits);
    topk_kernel<<<MROWS, 256, TK_SMEM>>>(logits, target);
    transmat_kernel<<<BATCH * (TLEN - 1), 256>>>(E1, E2);
    forward_kernel<<<BATCH, 64>>>(logits, target, E1, E2, losses);
}

// round 13
// speedup vs baseline: 2.6128x; 1.1988x over previous
#include <cuda_runtime.h>
#include <cuda_bf16.h>
#include <math.h>
#include <stdint.h>

#define BATCH   4
#define TLEN    512
#define EDIM    1024
#define VOCAB_N 32000
#define BEAM_N  64
#define RANK_N  32
#define MROWS   (BATCH * TLEN)

__device__ __align__(16) __nv_bfloat16 g_Ahi[MROWS * EDIM];
__device__ __align__(16) __nv_bfloat16 g_Alo[MROWS * EDIM];
__device__ __align__(16) __nv_bfloat16 g_Bhi[VOCAB_N * EDIM];
__device__ __align__(16) __nv_bfloat16 g_Blo[VOCAB_N * EDIM];
__device__ int   g_beams[MROWS * BEAM_N];
__device__ float g_bemit[MROWS * BEAM_N];
__device__ __align__(16) float g_tm[BATCH * (TLEN - 1) * BEAM_N * BEAM_N]; // exp(trans)

// ---------------------------------------------------------------- helpers --
__device__ __forceinline__ uint32_t s2u(const void* p) {
    uint32_t a;
    asm("{ .reg .u64 t; cvta.to.shared.u64 t, %1; cvt.u32.u64 %0, t; }" : "=r"(a) : "l"(p));
    return a;
}
__device__ __forceinline__ void cpasync16(uint32_t s, const void* g) {
    asm volatile("cp.async.cg.shared.global [%0], [%1], 16;" :: "r"(s), "l"(g) : "memory");
}
__device__ __forceinline__ void ldm4(uint32_t* f, uint32_t addr) {
    asm volatile("ldmatrix.sync.aligned.m8n8.x4.shared.b16 {%0,%1,%2,%3}, [%4];"
        : "=r"(f[0]), "=r"(f[1]), "=r"(f[2]), "=r"(f[3]) : "r"(addr));
}
__device__ __forceinline__ void mma16816(float* d, const uint32_t* a,
                                         uint32_t b0, uint32_t b1) {
    asm volatile("mma.sync.aligned.m16n8k16.row.col.f32.bf16.bf16.f32 "
        "{%0,%1,%2,%3}, {%4,%5,%6,%7}, {%8,%9}, {%0,%1,%2,%3};"
        : "+f"(d[0]), "+f"(d[1]), "+f"(d[2]), "+f"(d[3])
        : "r"(a[0]), "r"(a[1]), "r"(a[2]), "r"(a[3]), "r"(b0), "r"(b1));
}

// ============================ 0) fp32 -> bf16 hi/lo split ===================
__device__ __forceinline__ void split4(float4 v, uint2& uh, uint2& ul) {
    __nv_bfloat16 h0 = __float2bfloat16(v.x), h1 = __float2bfloat16(v.y);
    __nv_bfloat16 h2 = __float2bfloat16(v.z), h3 = __float2bfloat16(v.w);
    __nv_bfloat16 l0 = __float2bfloat16(v.x - __bfloat162float(h0));
    __nv_bfloat16 l1 = __float2bfloat16(v.y - __bfloat162float(h1));
    __nv_bfloat16 l2 = __float2bfloat16(v.z - __bfloat162float(h2));
    __nv_bfloat16 l3 = __float2bfloat16(v.w - __bfloat162float(h3));
    uh.x = ((unsigned)__bfloat16_as_ushort(h1) << 16) | __bfloat16_as_ushort(h0);
    uh.y = ((unsigned)__bfloat16_as_ushort(h3) << 16) | __bfloat16_as_ushort(h2);
    ul.x = ((unsigned)__bfloat16_as_ushort(l1) << 16) | __bfloat16_as_ushort(l0);
    ul.y = ((unsigned)__bfloat16_as_ushort(l3) << 16) | __bfloat16_as_ushort(l2);
}
__global__ void __launch_bounds__(256) convertA(const float4* __restrict__ src) {
    int i = blockIdx.x * 256 + threadIdx.x;
    uint2 uh, ul; split4(src[i], uh, ul);
    ((uint2*)g_Ahi)[i] = uh; ((uint2*)g_Alo)[i] = ul;
}
__global__ void __launch_bounds__(256) convertB(const float4* __restrict__ src) {
    int i = blockIdx.x * 256 + threadIdx.x;
    uint2 uh, ul; split4(src[i], uh, ul);
    ((uint2*)g_Bhi)[i] = uh; ((uint2*)g_Blo)[i] = ul;
}

// ============================ 1) mma.sync bf16 GEMM (unchanged) =============
#define BKI 32
#define KITERS (EDIM / BKI)
#define ROW_B 80
#define MAT_BYTES (128 * ROW_B)
#define STAGE_BYTES (4 * MAT_BYTES)
#define NSTAGE 2
#define GEMM_SMEM (NSTAGE * STAGE_BYTES)

__device__ __forceinline__ void load_stage(uint32_t sbase, int buf, int it,
                                           int tid, int row0, int col0) {
    uint32_t st = sbase + buf * STAGE_BYTES;
    int k0 = it * BKI;
#pragma unroll
    for (int j = 0; j < 8; j++) {
        int cid = tid + j * 256;
        int mat = cid >> 9;
        int rc  = cid & 511;
        int r = rc >> 2, c = rc & 3;
        const __nv_bfloat16* gp;
        if (mat == 0)      gp = g_Ahi + (size_t)(row0 + r) * EDIM + k0 + c * 8;
        else if (mat == 1) gp = g_Alo + (size_t)(row0 + r) * EDIM + k0 + c * 8;
        else if (mat == 2) gp = g_Bhi + (size_t)(col0 + r) * EDIM + k0 + c * 8;
        else               gp = g_Blo + (size_t)(col0 + r) * EDIM + k0 + c * 8;
        cpasync16(st + (uint32_t)(mat * MAT_BYTES + r * ROW_B + c * 16), gp);
    }
    asm volatile("cp.async.commit_group;" ::: "memory");
}

__global__ void __launch_bounds__(256, 2)
gemm_mma(const float* __restrict__ bias, float* __restrict__ C)
{
    extern __shared__ char smem[];
    uint32_t sbase = s2u(smem);
    int tid = threadIdx.x, lane = tid & 31, wid = tid >> 5;

    int bid = blockIdx.x;
    int grp = bid / 160, w = bid % 160;
    int row0 = (w & 15) * 128;
    int col0 = (grp * 10 + (w >> 4)) * 128;

    int warp_m = wid & 3;
    int warp_n = wid >> 2;

    float acc[2][8][4];
#pragma unroll
    for (int mi = 0; mi < 2; mi++)
#pragma unroll
        for (int ni = 0; ni < 8; ni++)
#pragma unroll
            for (int q = 0; q < 4; q++) acc[mi][ni][q] = 0.f;

    load_stage(sbase, 0, 0, tid, row0, col0);
    load_stage(sbase, 1, 1, tid, row0, col0);

    uint32_t aoff = (uint32_t)(warp_m * 32 + (lane & 15)) * ROW_B + ((lane >> 4) * 16);
    uint32_t boff = (uint32_t)(warp_n * 64 + (lane & 7) + ((lane >> 4) << 3)) * ROW_B
                  + (((lane >> 3) & 1) * 16);

    for (int it = 0; it < KITERS; it++) {
        if (it < KITERS - 1) asm volatile("cp.async.wait_group 1;" ::: "memory");
        else                 asm volatile("cp.async.wait_group 0;" ::: "memory");
        __syncthreads();

        uint32_t st = sbase + (uint32_t)((it & 1) * STAGE_BYTES);
#pragma unroll
        for (int ks = 0; ks < 2; ks++) {
            uint32_t kb = ks * 32;
            uint32_t ahi[2][4], alo[2][4];
#pragma unroll
            for (int mi = 0; mi < 2; mi++) {
                ldm4(ahi[mi], st + 0 * MAT_BYTES + mi * (16 * ROW_B) + aoff + kb);
                ldm4(alo[mi], st + 1 * MAT_BYTES + mi * (16 * ROW_B) + aoff + kb);
            }
#pragma unroll
            for (int nt = 0; nt < 4; nt++) {
                uint32_t bh[4], bl[4];
                ldm4(bh, st + 2 * MAT_BYTES + nt * (16 * ROW_B) + boff + kb);
                ldm4(bl, st + 3 * MAT_BYTES + nt * (16 * ROW_B) + boff + kb);
#pragma unroll
                for (int mi = 0; mi < 2; mi++) {
                    mma16816(acc[mi][nt*2+0], ahi[mi], bh[0], bh[1]);
                    mma16816(acc[mi][nt*2+1], ahi[mi], bh[2], bh[3]);
                    mma16816(acc[mi][nt*2+0], ahi[mi], bl[0], bl[1]);
                    mma16816(acc[mi][nt*2+1], ahi[mi], bl[2], bl[3]);
                    mma16816(acc[mi][nt*2+0], alo[mi], bh[0], bh[1]);
                    mma16816(acc[mi][nt*2+1], alo[mi], bh[2], bh[3]);
                }
            }
        }
        __syncthreads();
        if (it + 2 < KITERS) load_stage(sbase, it & 1, it + 2, tid, row0, col0);
    }

    int ti2 = (lane & 3) * 2, g8 = lane >> 2;
#pragma unroll
    for (int ni = 0; ni < 8; ni++) {
        int colg = col0 + warp_n * 64 + ni * 8 + ti2;
        float b0 = bias[colg], b1 = bias[colg + 1];
#pragma unroll
        for (int mi = 0; mi < 2; mi++) {
            int rowg = row0 + warp_m * 32 + mi * 16 + g8;
            float2 v0 = { acc[mi][ni][0] + b0, acc[mi][ni][1] + b1 };
            float2 v1 = { acc[mi][ni][2] + b0, acc[mi][ni][3] + b1 };
            *(float2*)(C + (size_t)rowg * VOCAB_N + colg) = v0;
            *(float2*)(C + (size_t)(rowg + 8) * VOCAB_N + colg) = v1;
        }
    }
}

// ============================ 2) top-64: 2-pass select ======================
#define TK_CAP 2048
#define TK_SMEM (2048 * 4 + TK_CAP * 8)   // 24576 bytes

__device__ __forceinline__ unsigned f2key(float x) {
    unsigned u = __float_as_uint(x);
    return (u & 0x80000000u) ? ~u : (u | 0x80000000u);
}

__global__ void __launch_bounds__(256)
topk_kernel(const float* __restrict__ logits, const int* __restrict__ target)
{
    extern __shared__ int tksh[];
    int* hist = tksh;                         // 2048 ints
    unsigned* ck = (unsigned*)(tksh + 2048);  // TK_CAP keys
    int* ci = (int*)(ck + TK_CAP);            // TK_CAP idxs

    __shared__ int s_bin, s_want, s_slot, s_pref, s_want2, cnt_eq, cnt_eq2;

    int row = blockIdx.x;
    const float* lrow = logits + (size_t)row * VOCAB_N;
    const float4* l4 = (const float4*)lrow;
    int tgt = target[row];
    int tid = threadIdx.x;

    for (int i = tid; i < 2048; i += 256) hist[i] = 0;
    __syncthreads();

    for (int i = tid; i < VOCAB_N / 4; i += 256) {
        float4 v = l4[i];
        atomicAdd(&hist[f2key(v.x) >> 21], 1);
        atomicAdd(&hist[f2key(v.y) >> 21], 1);
        atomicAdd(&hist[f2key(v.z) >> 21], 1);
        atomicAdd(&hist[f2key(v.w) >> 21], 1);
    }
    __syncthreads();
    if (tid == 0) {
        atomicAdd(&hist[f2key(lrow[tgt]) >> 21], -1);
        atomicAdd(&hist[2047], 1);
        int cum = 0, b;
        for (b = 2047; b >= 0; b--) {
            int c = hist[b];
            if (cum + c >= BEAM_N) break;
            cum += c;
        }
        s_bin = b; s_want = BEAM_N - cum; s_slot = 0; cnt_eq = 0;
    }
    __syncthreads();
    int bsel = s_bin;

    for (int i = tid; i < VOCAB_N / 4; i += 256) {
        float4 v = l4[i];
        float vv[4] = { v.x, v.y, v.z, v.w };
#pragma unroll
        for (int j = 0; j < 4; j++) {
            int idx = i * 4 + j;
            unsigned key = (idx == tgt) ? 0xFFFFFFFFu : f2key(vv[j]);
            int bin = (int)(key >> 21);
            if (bin > bsel) {
                int p = atomicAdd(&s_slot, 1);
                g_beams[row * BEAM_N + p] = idx;
            } else if (bin == bsel) {
                int p = atomicAdd(&cnt_eq, 1);
                if (p < TK_CAP) { ck[p] = key; ci[p] = idx; }
            }
        }
    }
    __syncthreads();
    int ncand = min(cnt_eq, TK_CAP);

    if (tid == 0) { s_pref = 0; s_want2 = s_want; }
    __syncthreads();
#pragma unroll
    for (int pass = 0; pass < 3; pass++) {
        int shift = 14 - pass * 7;
        for (int i = tid; i < 128; i += 256) hist[i] = 0;
        __syncthreads();
        int pref = s_pref;
        for (int j = tid; j < ncand; j += 256) {
            unsigned low = ck[j] & 0x1FFFFFu;
            if ((int)(low >> (shift + 7)) == pref)
                atomicAdd(&hist[(low >> shift) & 127], 1);
        }
        __syncthreads();
        if (tid == 0) {
            int want = s_want2, cum = 0, b;
            for (b = 127; b >= 0; b--) {
                int c = hist[b];
                if (cum + c >= want) break;
                cum += c;
            }
            s_pref = (pref << 7) | b;
            s_want2 = want - cum;
        }
        __syncthreads();
    }
    unsigned thresh = (unsigned)s_pref;
    if (tid == 0) cnt_eq2 = 0;
    __syncthreads();
    int wantEq = s_want2;
    for (int j = tid; j < ncand; j += 256) {
        unsigned low = ck[j] & 0x1FFFFFu;
        if (low > thresh) {
            int p = atomicAdd(&s_slot, 1);
            g_beams[row * BEAM_N + p] = ci[j];
        } else if (low == thresh) {
            int p = atomicAdd(&cnt_eq2, 1);
            if (p < wantEq) {
                int q = atomicAdd(&s_slot, 1);
                g_beams[row * BEAM_N + q] = ci[j];
            }
        }
    }
    __syncthreads();

    if (tid < BEAM_N) {
        int idx = g_beams[row * BEAM_N + tid];
        g_bemit[row * BEAM_N + tid] = lrow[idx];
    }
}

// ============================ 3) trans_mat -> exp(trans_mat) ================
__global__ void __launch_bounds__(256)
transmat_kernel(const float* __restrict__ E1, const float* __restrict__ E2)
{
    int bt = blockIdx.x;
    int b = bt / (TLEN - 1), t = bt % (TLEN - 1);
    int tid = threadIdx.x;
    __shared__ float s1[BEAM_N][RANK_N + 1];
    __shared__ float s2[BEAM_N][RANK_N + 1];
    const int* bm0 = g_beams + (size_t)(b * TLEN + t) * BEAM_N;
    const int* bm1 = bm0 + BEAM_N;
    for (int i = tid; i < BEAM_N * RANK_N; i += 256) {
        int k = i >> 5, r = i & 31;
        s1[k][r] = E1[(size_t)bm0[k] * RANK_N + r];
        s2[k][r] = E2[(size_t)bm1[k] * RANK_N + r];
    }
    __syncthreads();
    float* out = g_tm + (size_t)bt * (BEAM_N * BEAM_N);
    for (int o = tid; o < BEAM_N * BEAM_N; o += 256) {
        int kk = o >> 6, ll = o & 63;
        float acc = 0.f;
#pragma unroll
        for (int r = 0; r < RANK_N; r++) acc += s1[kk][r] * s2[ll][r];
        out[o] = expf(acc);                      // store exp(trans)
    }
}

// ============================ 4) forward recursion (exp-factored) ===========
__global__ void __launch_bounds__(256)
forward_kernel(const float* __restrict__ logits, const int* __restrict__ target,
               const float* __restrict__ E1, const float* __restrict__ E2,
               float* __restrict__ losses)
{
    __shared__ float sc[64], w[64], pmax[2];
    __shared__ float partial[256], red[256];
    __shared__ __align__(16) float etm[2][4096];
    int b = blockIdx.x, tid = threadIdx.x;
    int q = tid >> 6, l = tid & 63;

    float np = 0.f;
    for (int t = tid; t < TLEN; t += 256) {
        int tg = target[b * TLEN + t];
        if (tg != 0) {
            float e = logits[(size_t)(b * TLEN + t) * VOCAB_N + tg];
            float tr = 0.f;
            if (t > 0) {
                int tp = target[b * TLEN + t - 1];
#pragma unroll
                for (int r = 0; r < RANK_N; r++)
                    tr += E1[(size_t)tp * RANK_N + r] * E2[(size_t)tg * RANK_N + r];
            }
            np += e + tr;
        }
    }
    red[tid] = np;
    if (tid < 64) sc[tid] = g_bemit[(size_t)(b * TLEN) * BEAM_N + tid];

    uint32_t sb = s2u(etm);
    const float* tmbase = g_tm + (size_t)b * (TLEN - 1) * 4096;
#pragma unroll
    for (int j = 0; j < 4; j++) {
        int c = tid + j * 256;
        cpasync16(sb + (uint32_t)c * 16, tmbase + c * 4);
    }
    asm volatile("cp.async.commit_group;" ::: "memory");
    __syncthreads();

    for (int t = 1; t < TLEN; t++) {
        int cur = (t - 1) & 1;
        if (t < TLEN - 1) {
            const float* nb = tmbase + (size_t)t * 4096;
            uint32_t db = sb + (uint32_t)((t & 1) * 16384);
#pragma unroll
            for (int j = 0; j < 4; j++) {
                int c = tid + j * 256;
                cpasync16(db + (uint32_t)c * 16, nb + c * 4);
            }
            asm volatile("cp.async.commit_group;" ::: "memory");
        }
        if (tid < 64) {
            float v = sc[tid];
#pragma unroll
            for (int o = 16; o > 0; o >>= 1)
                v = fmaxf(v, __shfl_xor_sync(0xffffffffu, v, o));
            if ((tid & 31) == 0) pmax[tid >> 5] = v;
        }
        __syncthreads();
        float mx = fmaxf(pmax[0], pmax[1]);
        if (tid < 64) w[tid] = expf(sc[tid] - mx);
        if (t < TLEN - 1) asm volatile("cp.async.wait_group 1;" ::: "memory");
        else              asm volatile("cp.async.wait_group 0;" ::: "memory");
        __syncthreads();

        const float* et = etm[cur];
        float acc = 0.f;
#pragma unroll
        for (int i = 0; i < 16; i++) {
            int k = q * 16 + i;
            acc += w[k] * et[k * 64 + l];
        }
        partial[tid] = acc;
        __syncthreads();
        if (tid < 64) {
            float s = partial[tid] + partial[tid + 64] + partial[tid + 128] + partial[tid + 192];
            if (target[b * TLEN + t] != 0)
                sc[tid] = mx + logf(s) + g_bemit[(size_t)(b * TLEN + t) * BEAM_N + tid];
        }
        __syncthreads();
    }

    if (tid == 0) {
        float num = 0.f;
        for (int i = 0; i < 256; i++) num += red[i];
        float mx = sc[0];
        for (int i = 1; i < 64; i++) mx = fmaxf(mx, sc[i]);
        float s = 0.f;
        for (int i = 0; i < 64; i++) s += expf(sc[i] - mx);
        losses[b] = -(num - (mx + logf(s)));
    }
}

// ============================================================================
extern "C" void kernel_launch(void* const* d_in, const int* in_sizes, int n_in,
                              void* d_out, int out_size)
{
    const float* modelout = (const float*)d_in[0];
    const float* W        = (const float*)d_in[1];
    const float* bias     = (const float*)d_in[2];
    const float* E1       = (const float*)d_in[3];
    const float* E2       = (const float*)d_in[4];
    const int*   target   = (const int*)  d_in[5];

    float* logits = (float*)d_out;
    float* losses = logits + (size_t)MROWS * VOCAB_N;

    cudaFuncSetAttribute(gemm_mma, cudaFuncAttributeMaxDynamicSharedMemorySize, GEMM_SMEM);
    cudaFuncSetAttribute(topk_kernel, cudaFuncAttributeMaxDynamicSharedMemorySize, TK_SMEM);

    convertA<<<MROWS * EDIM / 1024, 256>>>((const float4*)modelout);
    convertB<<<VOCAB_N * EDIM / 1024, 256>>>((const float4*)W);
    gemm_mma<<<(VOCAB_N / 128) * (MROWS / 128), 256, GEMM_SMEM>>>(bias, logits);
    topk_kernel<<<MROWS, 256, TK_SMEM>>>(logits, target);
    transmat_kernel<<<BATCH * (TLEN - 1), 256>>>(E1, E2);
    forward_kernel<<<BATCH, 256>>>(logits, target, E1, E2, losses);
}